// round 12
// baseline (speedup 1.0000x reference)
#include <cuda_runtime.h>
#include <cuda_fp16.h>
#include <cstdint>

#define T_STEPS 1024
#define N_IN    4096
#define N_OUT   4096

// ---------------------------------------------------------------------------
// Device scratch (static globals — no allocations allowed)
// ---------------------------------------------------------------------------
__device__ __align__(16) float  g_cur[T_STEPS * N_OUT];     // 16 MB
__device__ __align__(16) __half g_xh[T_STEPS * N_IN];       // 8 MB
__device__ __align__(16) __half g_xl[T_STEPS * N_IN];       // 8 MB
__device__ __align__(16) __half g_Wh[(size_t)N_OUT * N_IN]; // 32 MB
__device__ __align__(16) __half g_Wl[(size_t)N_OUT * N_IN]; // 32 MB

// ---------------------------------------------------------------------------
// Helpers
// ---------------------------------------------------------------------------
__device__ __forceinline__ uint32_t smem_to_u32(const void* p) {
    uint32_t a;
    asm("{ .reg .u64 t; cvta.to.shared.u64 t, %1; cvt.u32.u64 %0, t; }" : "=r"(a) : "l"(p));
    return a;
}
__device__ __forceinline__ void cp16(uint32_t dst, const void* src) {
    asm volatile("cp.async.cg.shared.global [%0], [%1], 16;" :: "r"(dst), "l"(src));
}
#define CP_COMMIT() asm volatile("cp.async.commit_group;" ::: "memory")
#define CP_WAIT(n)  asm volatile("cp.async.wait_group %0;" :: "n"(n) : "memory")

__device__ __forceinline__ void ldsm_x4(uint32_t& r0, uint32_t& r1, uint32_t& r2, uint32_t& r3,
                                        uint32_t addr) {
    asm volatile("ldmatrix.sync.aligned.m8n8.x4.shared.b16 {%0,%1,%2,%3}, [%4];"
                 : "=r"(r0), "=r"(r1), "=r"(r2), "=r"(r3) : "r"(addr));
}
// fp16 inputs, fp32 accumulate
__device__ __forceinline__ void mma16816(float* c, const uint32_t* a, const uint32_t* b) {
    asm volatile("mma.sync.aligned.m16n8k16.row.col.f32.f16.f16.f32 "
                 "{%0,%1,%2,%3}, {%4,%5,%6,%7}, {%8,%9}, {%0,%1,%2,%3};"
                 : "+f"(c[0]), "+f"(c[1]), "+f"(c[2]), "+f"(c[3])
                 : "r"(a[0]), "r"(a[1]), "r"(a[2]), "r"(a[3]), "r"(b[0]), "r"(b[1]));
}
// fp16 inputs, fp16 accumulate (correction terms; flushed to fp32 per window)
__device__ __forceinline__ void mma16816_f16(uint32_t* c, const uint32_t* a, const uint32_t* b) {
    asm volatile("mma.sync.aligned.m16n8k16.row.col.f16.f16.f16.f16 "
                 "{%0,%1}, {%2,%3,%4,%5}, {%6,%7}, {%0,%1};"
                 : "+r"(c[0]), "+r"(c[1])
                 : "r"(a[0]), "r"(a[1]), "r"(a[2]), "r"(a[3]), "r"(b[0]), "r"(b[1]));
}

// ---------------------------------------------------------------------------
// Pre-pass: fp32 -> (fp16 hi, fp16 lo) split for BOTH x and W in one launch.
// ---------------------------------------------------------------------------
struct __align__(8) f16x4 { __half2 a, b; };

__device__ __forceinline__ void split4(const float4 v, f16x4& H, f16x4& L) {
    __half h0 = __float2half_rn(v.x);
    __half h1 = __float2half_rn(v.y);
    __half h2 = __float2half_rn(v.z);
    __half h3 = __float2half_rn(v.w);
    __half l0 = __float2half_rn(v.x - __half2float(h0));
    __half l1 = __float2half_rn(v.y - __half2float(h1));
    __half l2 = __float2half_rn(v.z - __half2float(h2));
    __half l3 = __float2half_rn(v.w - __half2float(h3));
    H.a = __halves2half2(h0, h1); H.b = __halves2half2(h2, h3);
    L.a = __halves2half2(l0, l1); L.b = __halves2half2(l2, l3);
}

__global__ void split2_kernel(const float4* __restrict__ x, const float4* __restrict__ W,
                              f16x4* __restrict__ xh, f16x4* __restrict__ xl,
                              f16x4* __restrict__ Wh, f16x4* __restrict__ Wl,
                              int n4x, int n4tot)
{
    int stride = gridDim.x * blockDim.x;
    for (int i = blockIdx.x * blockDim.x + threadIdx.x; i < n4tot; i += stride) {
        if (i < n4x) {
            f16x4 H, L; split4(x[i], H, L);
            xh[i] = H; xl[i] = L;
        } else {
            int j = i - n4x;
            f16x4 H, L; split4(W[j], H, L);
            Wh[j] = H; Wl[j] = L;
        }
    }
}

// ---------------------------------------------------------------------------
// fp16 mma.sync GEMM, hi/lo split. hh: fp32 windowed accumulation (256-k
// window). hl+lh: fp16 accumulator chain flushed per window (round-11 recipe).
// Loader rewritten in affine/immediate form: 4 running byte pointers +
// precomputed swizzle base; 8 cp.async with imm offsets per thread per stage.
// CTA tile 128x128, BK=64, NSTAGE=3 (192KB smem, occ 1), 512 thr / 16 warps.
// ---------------------------------------------------------------------------
#define BM 128
#define BN 128
#define BK 64
#define NSTAGE 3
#define TILE_BYTES (128 * 128)
#define STAGE_BYTES (4 * TILE_BYTES)         // Ah, Al, Bh, Bl
#define AH_OFF 0
#define AL_OFF (1 * TILE_BYTES)
#define BH_OFF (2 * TILE_BYTES)
#define BL_OFF (3 * TILE_BYTES)
#define SMEM_DYN_BYTES (NSTAGE * STAGE_BYTES)   // 196608
#define ROW_BYTES 8192                          // N_IN * sizeof(__half)
#define JSTRIDE_G (64 * ROW_BYTES)              // +64 rows in global = 524288 B
#define JSTRIDE_S (64 * 128)                    // +64 rows in smem tile = 8192 B

__device__ __forceinline__ uint32_t swz(uint32_t row, uint32_t chunk) {
    return row * 128u + ((chunk ^ (row & 7u)) << 4);
}

__global__ __launch_bounds__(512, 1)
void gemm_mma_kernel(const __half* __restrict__ Ah,
                     const __half* __restrict__ Al,
                     const __half* __restrict__ Bh,
                     const __half* __restrict__ Bl,
                     float* __restrict__ C)
{
    extern __shared__ char dsm[];
    const uint32_t smem = smem_to_u32(dsm);

    const int tid = threadIdx.x;
    const int wid = tid >> 5;
    const int lane = tid & 31;
    const int wr = wid >> 2;
    const int wc = wid & 3;
    const int wM = wr * 32;
    const int wN = wc * 32;

    const int bRow = blockIdx.y * BM;
    const int bCol = blockIdx.x * BN;

    const int lm_r8 = ((lane >> 3) & 1) * 8 + (lane & 7);
    const int lm_kh = lane >> 4;

    float acc_tot[2][4][4];
    float acc_win[2][4][4];
    uint32_t acc_c16[2][4][2];
    #pragma unroll
    for (int i = 0; i < 2; i++)
        #pragma unroll
        for (int j = 0; j < 4; j++) {
            #pragma unroll
            for (int k = 0; k < 4; k++) { acc_tot[i][j][k] = 0.0f; acc_win[i][j][k] = 0.0f; }
            acc_c16[i][j][0] = 0u; acc_c16[i][j][1] = 0u;
        }

    // ---- affine loader state ----
    // Thread covers rows {row0, row0+64} x chunk ch of each 128x128B tile.
    const uint32_t row0 = (uint32_t)tid >> 3;        // 0..63
    const uint32_t ch   = (uint32_t)tid & 7;         // 0..7
    // swizzled smem offset for (row0, ch); j-step adds JSTRIDE_S (row&7 invariant)
    const uint32_t off0 = row0 * 128u + ((ch ^ (row0 & 7u)) << 4);
    const size_t   g0   = (size_t)row0 * ROW_BYTES + ch * 16;

    const char* pAh = (const char*)Ah + (size_t)bRow * ROW_BYTES + g0;
    const char* pAl = (const char*)Al + (size_t)bRow * ROW_BYTES + g0;
    const char* pBh = (const char*)Bh + (size_t)bCol * ROW_BYTES + g0;
    const char* pBl = (const char*)Bl + (size_t)bCol * ROW_BYTES + g0;

    auto load_stage = [&](int s) {
        const uint32_t dst = smem + s * STAGE_BYTES + off0;
        cp16(dst + AH_OFF,             pAh);
        cp16(dst + AH_OFF + JSTRIDE_S, pAh + JSTRIDE_G);
        cp16(dst + AL_OFF,             pAl);
        cp16(dst + AL_OFF + JSTRIDE_S, pAl + JSTRIDE_G);
        cp16(dst + BH_OFF,             pBh);
        cp16(dst + BH_OFF + JSTRIDE_S, pBh + JSTRIDE_G);
        cp16(dst + BL_OFF,             pBl);
        cp16(dst + BL_OFF + JSTRIDE_S, pBl + JSTRIDE_G);
        CP_COMMIT();
        pAh += BK * 2; pAl += BK * 2; pBh += BK * 2; pBl += BK * 2;   // +128 B
    };

    load_stage(0);
    load_stage(1);

    const int NCHUNK = N_IN / BK;            // 64
    for (int c = 0; c < NCHUNK; c++) {
        const int s = c % NSTAGE;
        if (c < NCHUNK - 1) { CP_WAIT(1); } else { CP_WAIT(0); }
        __syncthreads();

        if (c + 2 < NCHUNK) load_stage((c + 2) % NSTAGE);

        const uint32_t st = smem + s * STAGE_BYTES;
        const uint32_t aH = st + AH_OFF, aL = st + AL_OFF;
        const uint32_t bH = st + BH_OFF, bL = st + BL_OFF;

        #pragma unroll
        for (int ks = 0; ks < BK / 16; ks++) {
            const uint32_t chunk = 2 * ks + lm_kh;

            uint32_t fAh[2][4], fAl[2][4];
            #pragma unroll
            for (int mt = 0; mt < 2; mt++) {
                const uint32_t row = wM + mt * 16 + lm_r8;
                const uint32_t off = swz(row, chunk);
                ldsm_x4(fAh[mt][0], fAh[mt][1], fAh[mt][2], fAh[mt][3], aH + off);
                ldsm_x4(fAl[mt][0], fAl[mt][1], fAl[mt][2], fAl[mt][3], aL + off);
            }
            uint32_t fBh[4][2], fBl[4][2];
            #pragma unroll
            for (int np = 0; np < 2; np++) {
                const uint32_t row = wN + np * 16 + lm_r8;
                const uint32_t off = swz(row, chunk);
                uint32_t r0, r1, r2, r3;
                ldsm_x4(r0, r1, r2, r3, bH + off);
                fBh[np * 2 + 0][0] = r0; fBh[np * 2 + 0][1] = r2;
                fBh[np * 2 + 1][0] = r1; fBh[np * 2 + 1][1] = r3;
                ldsm_x4(r0, r1, r2, r3, bL + off);
                fBl[np * 2 + 0][0] = r0; fBl[np * 2 + 0][1] = r2;
                fBl[np * 2 + 1][0] = r1; fBl[np * 2 + 1][1] = r3;
            }

            #pragma unroll
            for (int mt = 0; mt < 2; mt++)
                #pragma unroll
                for (int nt = 0; nt < 4; nt++) {
                    mma16816(acc_win[mt][nt], fAh[mt], fBh[nt]);        // hi*hi (fp32)
                    mma16816_f16(acc_c16[mt][nt], fAh[mt], fBl[nt]);    // hi*lo (fp16)
                    mma16816_f16(acc_c16[mt][nt], fAl[mt], fBh[nt]);    // lo*hi (fp16)
                }
        }

        // merge window every 4 chunks (256 k-values); flush fp16 corrections
        if ((c & 3) == 3) {
            #pragma unroll
            for (int mt = 0; mt < 2; mt++)
                #pragma unroll
                for (int nt = 0; nt < 4; nt++) {
                    __half2 h01 = *reinterpret_cast<__half2*>(&acc_c16[mt][nt][0]);
                    __half2 h23 = *reinterpret_cast<__half2*>(&acc_c16[mt][nt][1]);
                    acc_tot[mt][nt][0] += acc_win[mt][nt][0] + __half2float(h01.x);
                    acc_tot[mt][nt][1] += acc_win[mt][nt][1] + __half2float(h01.y);
                    acc_tot[mt][nt][2] += acc_win[mt][nt][2] + __half2float(h23.x);
                    acc_tot[mt][nt][3] += acc_win[mt][nt][3] + __half2float(h23.y);
                    #pragma unroll
                    for (int k = 0; k < 4; k++) acc_win[mt][nt][k] = 0.0f;
                    acc_c16[mt][nt][0] = 0u; acc_c16[mt][nt][1] = 0u;
                }
        }
    }

    // ---- epilogue ----
    const int lr = lane >> 2;
    const int lc = (lane & 3) * 2;
    #pragma unroll
    for (int mt = 0; mt < 2; mt++) {
        const int row0e = bRow + wM + mt * 16 + lr;
        #pragma unroll
        for (int nt = 0; nt < 4; nt++) {
            const int col = bCol + wN + nt * 8 + lc;
            float2 v0 = make_float2(acc_tot[mt][nt][0], acc_tot[mt][nt][1]);
            float2 v1 = make_float2(acc_tot[mt][nt][2], acc_tot[mt][nt][3]);
            *(float2*)(C + (size_t)row0e * N_OUT + col) = v0;
            *(float2*)(C + (size_t)(row0e + 8) * N_OUT + col) = v1;
        }
    }
}

// ---------------------------------------------------------------------------
// Leaky integrate-and-fire scan — exact round-1/5/7 arithmetic.
// 1 thread/neuron, 128 CTAs x 32 threads, 32-deep double-buffered prefetch.
// ---------------------------------------------------------------------------
__global__ __launch_bounds__(32)
void leaky_scan_kernel(const float* __restrict__ cur,
                       float* __restrict__ spk_out,
                       float* __restrict__ mem_out)
{
    const int n = blockIdx.x * 32 + threadIdx.x;   // 0..4095
    const float beta = 0.9f;
    const float thr  = 1.0f;

    float buf[32];
    #pragma unroll
    for (int i = 0; i < 32; i++) buf[i] = cur[(size_t)i * N_OUT + n];

    float mem = 0.0f;
    for (int t0 = 0; t0 < T_STEPS; t0 += 32) {
        float nxt[32];
        if (t0 + 32 < T_STEPS) {
            #pragma unroll
            for (int i = 0; i < 32; i++) nxt[i] = cur[(size_t)(t0 + 32 + i) * N_OUT + n];
        }
        #pragma unroll
        for (int i = 0; i < 32; i++) {
            const int t = t0 + i;
            float c = buf[i];
            float reset = (mem > thr) ? 1.0f : 0.0f;      // previous mem
            mem = beta * mem + c - reset * thr;
            float spk = (mem > thr) ? 1.0f : 0.0f;
            spk_out[(size_t)t * N_OUT + n] = spk;
            mem_out[(size_t)t * N_OUT + n] = mem;
        }
        #pragma unroll
        for (int i = 0; i < 32; i++) buf[i] = nxt[i];
    }
}

// ---------------------------------------------------------------------------
extern "C" void kernel_launch(void* const* d_in, const int* in_sizes, int n_in,
                              void* d_out, int out_size)
{
    const float* x = (const float*)d_in[0];   // [T, N_IN]
    const float* W = (const float*)d_in[1];   // [N_OUT, N_IN]
    float* out = (float*)d_out;               // [2, T, N_OUT]: spk then mem

    float* cur;   cudaGetSymbolAddress((void**)&cur, g_cur);
    __half *xh, *xl, *Wh, *Wl;
    cudaGetSymbolAddress((void**)&xh, g_xh);
    cudaGetSymbolAddress((void**)&xl, g_xl);
    cudaGetSymbolAddress((void**)&Wh, g_Wh);
    cudaGetSymbolAddress((void**)&Wl, g_Wl);

    const int n4x = T_STEPS * N_IN / 4;
    const int n4w = N_OUT * N_IN / 4;
    split2_kernel<<<2368, 256>>>((const float4*)x, (const float4*)W,
                                 (f16x4*)xh, (f16x4*)xl, (f16x4*)Wh, (f16x4*)Wl,
                                 n4x, n4x + n4w);

    cudaFuncSetAttribute(gemm_mma_kernel, cudaFuncAttributeMaxDynamicSharedMemorySize,
                         SMEM_DYN_BYTES);
    dim3 grid(N_OUT / BN, T_STEPS / BM);   // (32, 8) = 256 CTAs
    gemm_mma_kernel<<<grid, 512, SMEM_DYN_BYTES>>>(xh, xl, Wh, Wl, cur);

    float* spk = out;
    float* mem = out + (size_t)T_STEPS * N_OUT;
    leaky_scan_kernel<<<128, 32>>>(cur, spk, mem);
}

// round 13
// speedup vs baseline: 1.0299x; 1.0299x over previous
#include <cuda_runtime.h>
#include <cuda_fp16.h>
#include <cstdint>

#define T_STEPS 1024
#define N_IN    4096
#define N_OUT   4096

// ---------------------------------------------------------------------------
// Device scratch (static globals — no allocations allowed)
// ---------------------------------------------------------------------------
__device__ __align__(16) float  g_cur[T_STEPS * N_OUT];     // 16 MB
__device__ __align__(16) __half g_xh[T_STEPS * N_IN];       // 8 MB
__device__ __align__(16) __half g_xl[T_STEPS * N_IN];       // 8 MB
__device__ __align__(16) __half g_Wh[(size_t)N_OUT * N_IN]; // 32 MB
__device__ __align__(16) __half g_Wl[(size_t)N_OUT * N_IN]; // 32 MB

// ---------------------------------------------------------------------------
// Helpers
// ---------------------------------------------------------------------------
__device__ __forceinline__ uint32_t smem_to_u32(const void* p) {
    uint32_t a;
    asm("{ .reg .u64 t; cvta.to.shared.u64 t, %1; cvt.u32.u64 %0, t; }" : "=r"(a) : "l"(p));
    return a;
}
__device__ __forceinline__ void cp16(uint32_t dst, const void* src) {
    asm volatile("cp.async.cg.shared.global [%0], [%1], 16;" :: "r"(dst), "l"(src));
}
#define CP_COMMIT() asm volatile("cp.async.commit_group;" ::: "memory")
#define CP_WAIT(n)  asm volatile("cp.async.wait_group %0;" :: "n"(n) : "memory")

__device__ __forceinline__ void ldsm_x4(uint32_t& r0, uint32_t& r1, uint32_t& r2, uint32_t& r3,
                                        uint32_t addr) {
    asm volatile("ldmatrix.sync.aligned.m8n8.x4.shared.b16 {%0,%1,%2,%3}, [%4];"
                 : "=r"(r0), "=r"(r1), "=r"(r2), "=r"(r3) : "r"(addr));
}
// fp16 inputs, fp32 accumulate
__device__ __forceinline__ void mma16816(float* c, const uint32_t* a, const uint32_t* b) {
    asm volatile("mma.sync.aligned.m16n8k16.row.col.f32.f16.f16.f32 "
                 "{%0,%1,%2,%3}, {%4,%5,%6,%7}, {%8,%9}, {%0,%1,%2,%3};"
                 : "+f"(c[0]), "+f"(c[1]), "+f"(c[2]), "+f"(c[3])
                 : "r"(a[0]), "r"(a[1]), "r"(a[2]), "r"(a[3]), "r"(b[0]), "r"(b[1]));
}
// fp16 inputs, fp16 accumulate (correction terms; flushed to fp32 per window)
__device__ __forceinline__ void mma16816_f16(uint32_t* c, const uint32_t* a, const uint32_t* b) {
    asm volatile("mma.sync.aligned.m16n8k16.row.col.f16.f16.f16.f16 "
                 "{%0,%1}, {%2,%3,%4,%5}, {%6,%7}, {%0,%1};"
                 : "+r"(c[0]), "+r"(c[1])
                 : "r"(a[0]), "r"(a[1]), "r"(a[2]), "r"(a[3]), "r"(b[0]), "r"(b[1]));
}
// streaming store (evict-first; outputs are never re-read)
__device__ __forceinline__ void stcs(float* p, float v) {
    asm volatile("st.global.cs.f32 [%0], %1;" :: "l"(p), "f"(v));
}

// ---------------------------------------------------------------------------
// Pre-pass: fp32 -> (fp16 hi, fp16 lo) split for BOTH x and W in one launch.
// ---------------------------------------------------------------------------
struct __align__(8) f16x4 { __half2 a, b; };

__device__ __forceinline__ void split4(const float4 v, f16x4& H, f16x4& L) {
    __half h0 = __float2half_rn(v.x);
    __half h1 = __float2half_rn(v.y);
    __half h2 = __float2half_rn(v.z);
    __half h3 = __float2half_rn(v.w);
    __half l0 = __float2half_rn(v.x - __half2float(h0));
    __half l1 = __float2half_rn(v.y - __half2float(h1));
    __half l2 = __float2half_rn(v.z - __half2float(h2));
    __half l3 = __float2half_rn(v.w - __half2float(h3));
    H.a = __halves2half2(h0, h1); H.b = __halves2half2(h2, h3);
    L.a = __halves2half2(l0, l1); L.b = __halves2half2(l2, l3);
}

__global__ void split2_kernel(const float4* __restrict__ x, const float4* __restrict__ W,
                              f16x4* __restrict__ xh, f16x4* __restrict__ xl,
                              f16x4* __restrict__ Wh, f16x4* __restrict__ Wl,
                              int n4x, int n4tot)
{
    int stride = gridDim.x * blockDim.x;
    for (int i = blockIdx.x * blockDim.x + threadIdx.x; i < n4tot; i += stride) {
        if (i < n4x) {
            f16x4 H, L; split4(x[i], H, L);
            xh[i] = H; xl[i] = L;
        } else {
            int j = i - n4x;
            f16x4 H, L; split4(W[j], H, L);
            Wh[j] = H; Wl[j] = L;
        }
    }
}

// ---------------------------------------------------------------------------
// fp16 mma.sync GEMM — EXACT round-11 structure (356us known-good).
// hh: fp32 windowed accumulation (256-k window). hl+lh: fp16 accumulator
// chain flushed per window. CTA tile 128x128, BK=64, NSTAGE=3 (192KB, occ 1),
// 512 threads / 16 warps (4x4), warp tile 32x32.
// ---------------------------------------------------------------------------
#define BM 128
#define BN 128
#define BK 64
#define NSTAGE 3
#define TILE_BYTES (128 * 128)
#define STAGE_BYTES (4 * TILE_BYTES)         // Ah, Al, Bh, Bl
#define AH_OFF 0
#define AL_OFF (1 * TILE_BYTES)
#define BH_OFF (2 * TILE_BYTES)
#define BL_OFF (3 * TILE_BYTES)
#define SMEM_DYN_BYTES (NSTAGE * STAGE_BYTES)   // 196608

__device__ __forceinline__ uint32_t swz(uint32_t row, uint32_t chunk) {
    return row * 128u + ((chunk ^ (row & 7u)) << 4);
}

__global__ __launch_bounds__(512, 1)
void gemm_mma_kernel(const __half* __restrict__ Ah,
                     const __half* __restrict__ Al,
                     const __half* __restrict__ Bh,
                     const __half* __restrict__ Bl,
                     float* __restrict__ C)
{
    extern __shared__ char dsm[];
    const uint32_t smem = smem_to_u32(dsm);

    const int tid = threadIdx.x;
    const int wid = tid >> 5;
    const int lane = tid & 31;
    const int wr = wid >> 2;
    const int wc = wid & 3;
    const int wM = wr * 32;
    const int wN = wc * 32;

    const int bRow = blockIdx.y * BM;
    const int bCol = blockIdx.x * BN;

    const int lm_r8 = ((lane >> 3) & 1) * 8 + (lane & 7);
    const int lm_kh = lane >> 4;

    float acc_tot[2][4][4];
    float acc_win[2][4][4];
    uint32_t acc_c16[2][4][2];
    #pragma unroll
    for (int i = 0; i < 2; i++)
        #pragma unroll
        for (int j = 0; j < 4; j++) {
            #pragma unroll
            for (int k = 0; k < 4; k++) { acc_tot[i][j][k] = 0.0f; acc_win[i][j][k] = 0.0f; }
            acc_c16[i][j][0] = 0u; acc_c16[i][j][1] = 0u;
        }

    auto load_stage = [&](int c, int s) {
        const uint32_t st = smem + s * STAGE_BYTES;
        const size_t koff = (size_t)c * BK;
        const __half* aH = Ah + (size_t)bRow * N_IN + koff;
        const __half* aL = Al + (size_t)bRow * N_IN + koff;
        const __half* bH = Bh + (size_t)bCol * N_IN + koff;
        const __half* bL = Bl + (size_t)bCol * N_IN + koff;
        #pragma unroll
        for (int i = tid; i < 128 * 8; i += 512) {
            const uint32_t row = i >> 3, ch = i & 7;
            const uint32_t off = swz(row, ch);
            const size_t g = (size_t)row * N_IN + ch * 8;
            cp16(st + AH_OFF + off, aH + g);
            cp16(st + AL_OFF + off, aL + g);
            cp16(st + BH_OFF + off, bH + g);
            cp16(st + BL_OFF + off, bL + g);
        }
        CP_COMMIT();
    };

    load_stage(0, 0);
    load_stage(1, 1);

    const int NCHUNK = N_IN / BK;            // 64
    for (int c = 0; c < NCHUNK; c++) {
        const int s = c % NSTAGE;
        if (c < NCHUNK - 1) { CP_WAIT(1); } else { CP_WAIT(0); }
        __syncthreads();

        if (c + 2 < NCHUNK) load_stage(c + 2, (c + 2) % NSTAGE);

        const uint32_t st = smem + s * STAGE_BYTES;
        const uint32_t aH = st + AH_OFF, aL = st + AL_OFF;
        const uint32_t bH = st + BH_OFF, bL = st + BL_OFF;

        #pragma unroll
        for (int ks = 0; ks < BK / 16; ks++) {
            const uint32_t chunk = 2 * ks + lm_kh;

            uint32_t fAh[2][4], fAl[2][4];
            #pragma unroll
            for (int mt = 0; mt < 2; mt++) {
                const uint32_t row = wM + mt * 16 + lm_r8;
                const uint32_t off = swz(row, chunk);
                ldsm_x4(fAh[mt][0], fAh[mt][1], fAh[mt][2], fAh[mt][3], aH + off);
                ldsm_x4(fAl[mt][0], fAl[mt][1], fAl[mt][2], fAl[mt][3], aL + off);
            }
            uint32_t fBh[4][2], fBl[4][2];
            #pragma unroll
            for (int np = 0; np < 2; np++) {
                const uint32_t row = wN + np * 16 + lm_r8;
                const uint32_t off = swz(row, chunk);
                uint32_t r0, r1, r2, r3;
                ldsm_x4(r0, r1, r2, r3, bH + off);
                fBh[np * 2 + 0][0] = r0; fBh[np * 2 + 0][1] = r2;
                fBh[np * 2 + 1][0] = r1; fBh[np * 2 + 1][1] = r3;
                ldsm_x4(r0, r1, r2, r3, bL + off);
                fBl[np * 2 + 0][0] = r0; fBl[np * 2 + 0][1] = r2;
                fBl[np * 2 + 1][0] = r1; fBl[np * 2 + 1][1] = r3;
            }

            #pragma unroll
            for (int mt = 0; mt < 2; mt++)
                #pragma unroll
                for (int nt = 0; nt < 4; nt++) {
                    mma16816(acc_win[mt][nt], fAh[mt], fBh[nt]);        // hi*hi (fp32)
                    mma16816_f16(acc_c16[mt][nt], fAh[mt], fBl[nt]);    // hi*lo (fp16)
                    mma16816_f16(acc_c16[mt][nt], fAl[mt], fBh[nt]);    // lo*hi (fp16)
                }
        }

        // merge window every 4 chunks (256 k-values); flush fp16 corrections
        if ((c & 3) == 3) {
            #pragma unroll
            for (int mt = 0; mt < 2; mt++)
                #pragma unroll
                for (int nt = 0; nt < 4; nt++) {
                    __half2 h01 = *reinterpret_cast<__half2*>(&acc_c16[mt][nt][0]);
                    __half2 h23 = *reinterpret_cast<__half2*>(&acc_c16[mt][nt][1]);
                    acc_tot[mt][nt][0] += acc_win[mt][nt][0] + __half2float(h01.x);
                    acc_tot[mt][nt][1] += acc_win[mt][nt][1] + __half2float(h01.y);
                    acc_tot[mt][nt][2] += acc_win[mt][nt][2] + __half2float(h23.x);
                    acc_tot[mt][nt][3] += acc_win[mt][nt][3] + __half2float(h23.y);
                    #pragma unroll
                    for (int k = 0; k < 4; k++) acc_win[mt][nt][k] = 0.0f;
                    acc_c16[mt][nt][0] = 0u; acc_c16[mt][nt][1] = 0u;
                }
        }
    }

    // ---- epilogue ----
    const int lr = lane >> 2;
    const int lc = (lane & 3) * 2;
    #pragma unroll
    for (int mt = 0; mt < 2; mt++) {
        const int row0 = bRow + wM + mt * 16 + lr;
        #pragma unroll
        for (int nt = 0; nt < 4; nt++) {
            const int col = bCol + wN + nt * 8 + lc;
            float2 v0 = make_float2(acc_tot[mt][nt][0], acc_tot[mt][nt][1]);
            float2 v1 = make_float2(acc_tot[mt][nt][2], acc_tot[mt][nt][3]);
            *(float2*)(C + (size_t)row0 * N_OUT + col) = v0;
            *(float2*)(C + (size_t)(row0 + 8) * N_OUT + col) = v1;
        }
    }
}

// ---------------------------------------------------------------------------
// Leaky integrate-and-fire scan — exact round-1/5/7 arithmetic.
// 1 thread/neuron, 128 CTAs x 32 threads, 32-deep double-buffered prefetch.
// Loads via L2 (__ldcg); output stores streaming (.cs) — never re-read.
// ---------------------------------------------------------------------------
__global__ __launch_bounds__(32)
void leaky_scan_kernel(const float* __restrict__ cur,
                       float* __restrict__ spk_out,
                       float* __restrict__ mem_out)
{
    const int n = blockIdx.x * 32 + threadIdx.x;   // 0..4095
    const float beta = 0.9f;
    const float thr  = 1.0f;

    float buf[32];
    #pragma unroll
    for (int i = 0; i < 32; i++) buf[i] = __ldcg(&cur[(size_t)i * N_OUT + n]);

    float mem = 0.0f;
    for (int t0 = 0; t0 < T_STEPS; t0 += 32) {
        float nxt[32];
        if (t0 + 32 < T_STEPS) {
            #pragma unroll
            for (int i = 0; i < 32; i++) nxt[i] = __ldcg(&cur[(size_t)(t0 + 32 + i) * N_OUT + n]);
        }
        #pragma unroll
        for (int i = 0; i < 32; i++) {
            const int t = t0 + i;
            float c = buf[i];
            float reset = (mem > thr) ? 1.0f : 0.0f;      // previous mem
            mem = beta * mem + c - reset * thr;
            float spk = (mem > thr) ? 1.0f : 0.0f;
            stcs(&spk_out[(size_t)t * N_OUT + n], spk);
            stcs(&mem_out[(size_t)t * N_OUT + n], mem);
        }
        #pragma unroll
        for (int i = 0; i < 32; i++) buf[i] = nxt[i];
    }
}

// ---------------------------------------------------------------------------
extern "C" void kernel_launch(void* const* d_in, const int* in_sizes, int n_in,
                              void* d_out, int out_size)
{
    const float* x = (const float*)d_in[0];   // [T, N_IN]
    const float* W = (const float*)d_in[1];   // [N_OUT, N_IN]
    float* out = (float*)d_out;               // [2, T, N_OUT]: spk then mem

    float* cur;   cudaGetSymbolAddress((void**)&cur, g_cur);
    __half *xh, *xl, *Wh, *Wl;
    cudaGetSymbolAddress((void**)&xh, g_xh);
    cudaGetSymbolAddress((void**)&xl, g_xl);
    cudaGetSymbolAddress((void**)&Wh, g_Wh);
    cudaGetSymbolAddress((void**)&Wl, g_Wl);

    const int n4x = T_STEPS * N_IN / 4;
    const int n4w = N_OUT * N_IN / 4;
    split2_kernel<<<2368, 256>>>((const float4*)x, (const float4*)W,
                                 (f16x4*)xh, (f16x4*)xl, (f16x4*)Wh, (f16x4*)Wl,
                                 n4x, n4x + n4w);

    cudaFuncSetAttribute(gemm_mma_kernel, cudaFuncAttributeMaxDynamicSharedMemorySize,
                         SMEM_DYN_BYTES);
    dim3 grid(N_OUT / BN, T_STEPS / BM);   // (32, 8) = 256 CTAs
    gemm_mma_kernel<<<grid, 512, SMEM_DYN_BYTES>>>(xh, xl, Wh, Wl, cur);

    float* spk = out;
    float* mem = out + (size_t)T_STEPS * N_OUT;
    leaky_scan_kernel<<<128, 32>>>(cur, spk, mem);
}

// round 14
// speedup vs baseline: 1.0347x; 1.0046x over previous
#include <cuda_runtime.h>
#include <cuda_fp16.h>
#include <cstdint>

#define T_STEPS 1024
#define N_IN    4096
#define N_OUT   4096

// ---------------------------------------------------------------------------
// Device scratch (static globals — no allocations allowed)
// ---------------------------------------------------------------------------
__device__ __align__(16) float  g_cur[T_STEPS * N_OUT];     // 16 MB
__device__ __align__(16) __half g_xh[T_STEPS * N_IN];       // 8 MB
__device__ __align__(16) __half g_xl[T_STEPS * N_IN];       // 8 MB
__device__ __align__(16) __half g_Wh[(size_t)N_OUT * N_IN]; // 32 MB
__device__ __align__(16) __half g_Wl[(size_t)N_OUT * N_IN]; // 32 MB

// ---------------------------------------------------------------------------
// Helpers
// ---------------------------------------------------------------------------
__device__ __forceinline__ uint32_t smem_to_u32(const void* p) {
    uint32_t a;
    asm("{ .reg .u64 t; cvta.to.shared.u64 t, %1; cvt.u32.u64 %0, t; }" : "=r"(a) : "l"(p));
    return a;
}
__device__ __forceinline__ void cp16(uint32_t dst, const void* src) {
    asm volatile("cp.async.cg.shared.global [%0], [%1], 16;" :: "r"(dst), "l"(src));
}
#define CP_COMMIT() asm volatile("cp.async.commit_group;" ::: "memory")
#define CP_WAIT(n)  asm volatile("cp.async.wait_group %0;" :: "n"(n) : "memory")

__device__ __forceinline__ void ldsm_x4(uint32_t& r0, uint32_t& r1, uint32_t& r2, uint32_t& r3,
                                        uint32_t addr) {
    asm volatile("ldmatrix.sync.aligned.m8n8.x4.shared.b16 {%0,%1,%2,%3}, [%4];"
                 : "=r"(r0), "=r"(r1), "=r"(r2), "=r"(r3) : "r"(addr));
}
// fp16 inputs, fp32 accumulate
__device__ __forceinline__ void mma16816(float* c, const uint32_t* a, const uint32_t* b) {
    asm volatile("mma.sync.aligned.m16n8k16.row.col.f32.f16.f16.f32 "
                 "{%0,%1,%2,%3}, {%4,%5,%6,%7}, {%8,%9}, {%0,%1,%2,%3};"
                 : "+f"(c[0]), "+f"(c[1]), "+f"(c[2]), "+f"(c[3])
                 : "r"(a[0]), "r"(a[1]), "r"(a[2]), "r"(a[3]), "r"(b[0]), "r"(b[1]));
}
// fp16 inputs, fp16 accumulate (correction terms; flushed to fp32 per window)
__device__ __forceinline__ void mma16816_f16(uint32_t* c, const uint32_t* a, const uint32_t* b) {
    asm volatile("mma.sync.aligned.m16n8k16.row.col.f16.f16.f16.f16 "
                 "{%0,%1}, {%2,%3,%4,%5}, {%6,%7}, {%0,%1};"
                 : "+r"(c[0]), "+r"(c[1])
                 : "r"(a[0]), "r"(a[1]), "r"(a[2]), "r"(a[3]), "r"(b[0]), "r"(b[1]));
}
// streaming store (evict-first; outputs are never re-read)
__device__ __forceinline__ void stcs(float* p, float v) {
    asm volatile("st.global.cs.f32 [%0], %1;" :: "l"(p), "f"(v));
}

// ---------------------------------------------------------------------------
// Pre-pass: fp32 -> (fp16 hi, fp16 lo) split for BOTH x and W in one launch.
// ---------------------------------------------------------------------------
struct __align__(8) f16x4 { __half2 a, b; };

__device__ __forceinline__ void split4(const float4 v, f16x4& H, f16x4& L) {
    __half h0 = __float2half_rn(v.x);
    __half h1 = __float2half_rn(v.y);
    __half h2 = __float2half_rn(v.z);
    __half h3 = __float2half_rn(v.w);
    __half l0 = __float2half_rn(v.x - __half2float(h0));
    __half l1 = __float2half_rn(v.y - __half2float(h1));
    __half l2 = __float2half_rn(v.z - __half2float(h2));
    __half l3 = __float2half_rn(v.w - __half2float(h3));
    H.a = __halves2half2(h0, h1); H.b = __halves2half2(h2, h3);
    L.a = __halves2half2(l0, l1); L.b = __halves2half2(l2, l3);
}

__global__ void split2_kernel(const float4* __restrict__ x, const float4* __restrict__ W,
                              f16x4* __restrict__ xh, f16x4* __restrict__ xl,
                              f16x4* __restrict__ Wh, f16x4* __restrict__ Wl,
                              int n4x, int n4tot)
{
    int stride = gridDim.x * blockDim.x;
    for (int i = blockIdx.x * blockDim.x + threadIdx.x; i < n4tot; i += stride) {
        if (i < n4x) {
            f16x4 H, L; split4(x[i], H, L);
            xh[i] = H; xl[i] = L;
        } else {
            int j = i - n4x;
            f16x4 H, L; split4(W[j], H, L);
            Wh[j] = H; Wl[j] = L;
        }
    }
}

// ---------------------------------------------------------------------------
// fp16 mma.sync GEMM — EXACT round-11/13 structure (at the HMMA pipe floor).
// hh: fp32 windowed accumulation (256-k window). hl+lh: fp16 accumulator
// chain flushed per window. CTA tile 128x128, BK=64, NSTAGE=3 (192KB, occ 1),
// 512 threads / 16 warps (4x4), warp tile 32x32.
// ---------------------------------------------------------------------------
#define BM 128
#define BN 128
#define BK 64
#define NSTAGE 3
#define TILE_BYTES (128 * 128)
#define STAGE_BYTES (4 * TILE_BYTES)         // Ah, Al, Bh, Bl
#define AH_OFF 0
#define AL_OFF (1 * TILE_BYTES)
#define BH_OFF (2 * TILE_BYTES)
#define BL_OFF (3 * TILE_BYTES)
#define SMEM_DYN_BYTES (NSTAGE * STAGE_BYTES)   // 196608

__device__ __forceinline__ uint32_t swz(uint32_t row, uint32_t chunk) {
    return row * 128u + ((chunk ^ (row & 7u)) << 4);
}

__global__ __launch_bounds__(512, 1)
void gemm_mma_kernel(const __half* __restrict__ Ah,
                     const __half* __restrict__ Al,
                     const __half* __restrict__ Bh,
                     const __half* __restrict__ Bl,
                     float* __restrict__ C)
{
    extern __shared__ char dsm[];
    const uint32_t smem = smem_to_u32(dsm);

    const int tid = threadIdx.x;
    const int wid = tid >> 5;
    const int lane = tid & 31;
    const int wr = wid >> 2;
    const int wc = wid & 3;
    const int wM = wr * 32;
    const int wN = wc * 32;

    const int bRow = blockIdx.y * BM;
    const int bCol = blockIdx.x * BN;

    const int lm_r8 = ((lane >> 3) & 1) * 8 + (lane & 7);
    const int lm_kh = lane >> 4;

    float acc_tot[2][4][4];
    float acc_win[2][4][4];
    uint32_t acc_c16[2][4][2];
    #pragma unroll
    for (int i = 0; i < 2; i++)
        #pragma unroll
        for (int j = 0; j < 4; j++) {
            #pragma unroll
            for (int k = 0; k < 4; k++) { acc_tot[i][j][k] = 0.0f; acc_win[i][j][k] = 0.0f; }
            acc_c16[i][j][0] = 0u; acc_c16[i][j][1] = 0u;
        }

    auto load_stage = [&](int c, int s) {
        const uint32_t st = smem + s * STAGE_BYTES;
        const size_t koff = (size_t)c * BK;
        const __half* aH = Ah + (size_t)bRow * N_IN + koff;
        const __half* aL = Al + (size_t)bRow * N_IN + koff;
        const __half* bH = Bh + (size_t)bCol * N_IN + koff;
        const __half* bL = Bl + (size_t)bCol * N_IN + koff;
        #pragma unroll
        for (int i = tid; i < 128 * 8; i += 512) {
            const uint32_t row = i >> 3, ch = i & 7;
            const uint32_t off = swz(row, ch);
            const size_t g = (size_t)row * N_IN + ch * 8;
            cp16(st + AH_OFF + off, aH + g);
            cp16(st + AL_OFF + off, aL + g);
            cp16(st + BH_OFF + off, bH + g);
            cp16(st + BL_OFF + off, bL + g);
        }
        CP_COMMIT();
    };

    load_stage(0, 0);
    load_stage(1, 1);

    const int NCHUNK = N_IN / BK;            // 64
    for (int c = 0; c < NCHUNK; c++) {
        const int s = c % NSTAGE;
        if (c < NCHUNK - 1) { CP_WAIT(1); } else { CP_WAIT(0); }
        __syncthreads();

        if (c + 2 < NCHUNK) load_stage(c + 2, (c + 2) % NSTAGE);

        const uint32_t st = smem + s * STAGE_BYTES;
        const uint32_t aH = st + AH_OFF, aL = st + AL_OFF;
        const uint32_t bH = st + BH_OFF, bL = st + BL_OFF;

        #pragma unroll
        for (int ks = 0; ks < BK / 16; ks++) {
            const uint32_t chunk = 2 * ks + lm_kh;

            uint32_t fAh[2][4], fAl[2][4];
            #pragma unroll
            for (int mt = 0; mt < 2; mt++) {
                const uint32_t row = wM + mt * 16 + lm_r8;
                const uint32_t off = swz(row, chunk);
                ldsm_x4(fAh[mt][0], fAh[mt][1], fAh[mt][2], fAh[mt][3], aH + off);
                ldsm_x4(fAl[mt][0], fAl[mt][1], fAl[mt][2], fAl[mt][3], aL + off);
            }
            uint32_t fBh[4][2], fBl[4][2];
            #pragma unroll
            for (int np = 0; np < 2; np++) {
                const uint32_t row = wN + np * 16 + lm_r8;
                const uint32_t off = swz(row, chunk);
                uint32_t r0, r1, r2, r3;
                ldsm_x4(r0, r1, r2, r3, bH + off);
                fBh[np * 2 + 0][0] = r0; fBh[np * 2 + 0][1] = r2;
                fBh[np * 2 + 1][0] = r1; fBh[np * 2 + 1][1] = r3;
                ldsm_x4(r0, r1, r2, r3, bL + off);
                fBl[np * 2 + 0][0] = r0; fBl[np * 2 + 0][1] = r2;
                fBl[np * 2 + 1][0] = r1; fBl[np * 2 + 1][1] = r3;
            }

            #pragma unroll
            for (int mt = 0; mt < 2; mt++)
                #pragma unroll
                for (int nt = 0; nt < 4; nt++) {
                    mma16816(acc_win[mt][nt], fAh[mt], fBh[nt]);        // hi*hi (fp32)
                    mma16816_f16(acc_c16[mt][nt], fAh[mt], fBl[nt]);    // hi*lo (fp16)
                    mma16816_f16(acc_c16[mt][nt], fAl[mt], fBh[nt]);    // lo*hi (fp16)
                }
        }

        // merge window every 4 chunks (256 k-values); flush fp16 corrections
        if ((c & 3) == 3) {
            #pragma unroll
            for (int mt = 0; mt < 2; mt++)
                #pragma unroll
                for (int nt = 0; nt < 4; nt++) {
                    __half2 h01 = *reinterpret_cast<__half2*>(&acc_c16[mt][nt][0]);
                    __half2 h23 = *reinterpret_cast<__half2*>(&acc_c16[mt][nt][1]);
                    acc_tot[mt][nt][0] += acc_win[mt][nt][0] + __half2float(h01.x);
                    acc_tot[mt][nt][1] += acc_win[mt][nt][1] + __half2float(h01.y);
                    acc_tot[mt][nt][2] += acc_win[mt][nt][2] + __half2float(h23.x);
                    acc_tot[mt][nt][3] += acc_win[mt][nt][3] + __half2float(h23.y);
                    #pragma unroll
                    for (int k = 0; k < 4; k++) acc_win[mt][nt][k] = 0.0f;
                    acc_c16[mt][nt][0] = 0u; acc_c16[mt][nt][1] = 0u;
                }
        }
    }

    // ---- epilogue ----
    const int lr = lane >> 2;
    const int lc = (lane & 3) * 2;
    #pragma unroll
    for (int mt = 0; mt < 2; mt++) {
        const int row0 = bRow + wM + mt * 16 + lr;
        #pragma unroll
        for (int nt = 0; nt < 4; nt++) {
            const int col = bCol + wN + nt * 8 + lc;
            float2 v0 = make_float2(acc_tot[mt][nt][0], acc_tot[mt][nt][1]);
            float2 v1 = make_float2(acc_tot[mt][nt][2], acc_tot[mt][nt][3]);
            *(float2*)(C + (size_t)row0 * N_OUT + col) = v0;
            *(float2*)(C + (size_t)(row0 + 8) * N_OUT + col) = v1;
        }
    }
}

// ---------------------------------------------------------------------------
// Leaky integrate-and-fire scan — exact round-1/5/7 arithmetic.
// 1 thread/neuron, 256 CTAs x 16 threads (spreads chains over ~2 SMSPs/SM
// instead of 1), 32-deep double-buffered prefetch. __ldcg loads, .cs stores.
// ---------------------------------------------------------------------------
__global__ __launch_bounds__(16)
void leaky_scan_kernel(const float* __restrict__ cur,
                       float* __restrict__ spk_out,
                       float* __restrict__ mem_out)
{
    const int n = blockIdx.x * 16 + threadIdx.x;   // 0..4095
    const float beta = 0.9f;
    const float thr  = 1.0f;

    float buf[32];
    #pragma unroll
    for (int i = 0; i < 32; i++) buf[i] = __ldcg(&cur[(size_t)i * N_OUT + n]);

    float mem = 0.0f;
    for (int t0 = 0; t0 < T_STEPS; t0 += 32) {
        float nxt[32];
        if (t0 + 32 < T_STEPS) {
            #pragma unroll
            for (int i = 0; i < 32; i++) nxt[i] = __ldcg(&cur[(size_t)(t0 + 32 + i) * N_OUT + n]);
        }
        #pragma unroll
        for (int i = 0; i < 32; i++) {
            const int t = t0 + i;
            float c = buf[i];
            float reset = (mem > thr) ? 1.0f : 0.0f;      // previous mem
            mem = beta * mem + c - reset * thr;
            float spk = (mem > thr) ? 1.0f : 0.0f;
            stcs(&spk_out[(size_t)t * N_OUT + n], spk);
            stcs(&mem_out[(size_t)t * N_OUT + n], mem);
        }
        #pragma unroll
        for (int i = 0; i < 32; i++) buf[i] = nxt[i];
    }
}

// ---------------------------------------------------------------------------
extern "C" void kernel_launch(void* const* d_in, const int* in_sizes, int n_in,
                              void* d_out, int out_size)
{
    const float* x = (const float*)d_in[0];   // [T, N_IN]
    const float* W = (const float*)d_in[1];   // [N_OUT, N_IN]
    float* out = (float*)d_out;               // [2, T, N_OUT]: spk then mem

    float* cur;   cudaGetSymbolAddress((void**)&cur, g_cur);
    __half *xh, *xl, *Wh, *Wl;
    cudaGetSymbolAddress((void**)&xh, g_xh);
    cudaGetSymbolAddress((void**)&xl, g_xl);
    cudaGetSymbolAddress((void**)&Wh, g_Wh);
    cudaGetSymbolAddress((void**)&Wl, g_Wl);

    const int n4x = T_STEPS * N_IN / 4;
    const int n4w = N_OUT * N_IN / 4;
    split2_kernel<<<2368, 256>>>((const float4*)x, (const float4*)W,
                                 (f16x4*)xh, (f16x4*)xl, (f16x4*)Wh, (f16x4*)Wl,
                                 n4x, n4x + n4w);

    cudaFuncSetAttribute(gemm_mma_kernel, cudaFuncAttributeMaxDynamicSharedMemorySize,
                         SMEM_DYN_BYTES);
    dim3 grid(N_OUT / BN, T_STEPS / BM);   // (32, 8) = 256 CTAs
    gemm_mma_kernel<<<grid, 512, SMEM_DYN_BYTES>>>(xh, xl, Wh, Wl, cur);

    float* spk = out;
    float* mem = out + (size_t)T_STEPS * N_OUT;
    leaky_scan_kernel<<<256, 16>>>(cur, spk, mem);
}